// round 14
// baseline (speedup 1.0000x reference)
#include <cuda_runtime.h>
#include <cuda_bf16.h>
#include <math.h>
#include <stdint.h>

#define BB 64
#define TT 512
#define DIN 512
#define HH 1024

// rnn grid: 32 col-groups x 4 row-groups = 128 blocks
#define NCOLBLK 32
#define NROWGRP 4
#define RNBLK (NCOLBLK * NROWGRP)
#define NCOLS 32     // hidden cols per block
#define NROWS 16     // batch rows per block
#define NTHR 256

// rnn SMEM layout (bytes; 16B-aligned) — identical to R9
#define WROWB 2064                 // W row stride: 1024 bf16 + 8 pad
#define CROWB 1040                 // A chunk row stride: 512 bf16 + 8 pad
#define CPLANE (NROWS * CROWB)     // 16640 (one hi or lo plane of a chunk)
#define CBUF (2 * CPLANE)          // 33280 (hi+lo)
#define SM_WHI 0
#define SM_WLO (NCOLS * WROWB)     // 66048
#define SM_A0  (2 * NCOLS * WROWB) // 132096
#define SM_A1  (SM_A0 + CBUF)      // 165376
#define SM_PRE (SM_A1 + CBUF)      // 198656 (16x32 fp32 pre tile)
#define SM_SCR (SM_PRE + 2048)     // 200704 (fp32 partial-C scratch)
#define SM_TOTAL (SM_SCR + 2048)   // 202752

// Scratch: buf0 holds pre0 then h0 in place; buf1 holds pre1. h1 -> d_out.
__device__ float g_buf0[(size_t)BB * TT * HH];
__device__ float g_buf1[(size_t)BB * TT * HH];
// Current h(t) as bf16 hi/lo split (rewritten every step)
__device__ __nv_bfloat16 g_hhi[(size_t)BB * HH];
__device__ __nv_bfloat16 g_hlo[(size_t)BB * HH];
// bf16 hi/lo split of the big GEMM A operand (X, then H0) and W operand
__device__ __nv_bfloat16 g_ahi[(size_t)BB * TT * HH];
__device__ __nv_bfloat16 g_alo[(size_t)BB * TT * HH];
__device__ __nv_bfloat16 g_whi[(size_t)HH * HH];
__device__ __nv_bfloat16 g_wlo[(size_t)HH * HH];

// Per-row-group grid barriers (32 arrivals each; generation-based, R9 style)
__device__ unsigned int          g_bar_count[NROWGRP];
__device__ volatile unsigned int g_bar_gen[NROWGRP];

// ---------------------- PTX helpers (sm_90-class features) ----------------
__device__ __forceinline__ uint32_t smem_u32(const void* p) {
    uint32_t a;
    asm("{ .reg .u64 t; cvta.to.shared.u64 t, %1; cvt.u32.u64 %0, t; }"
        : "=r"(a) : "l"(p));
    return a;
}
__device__ __forceinline__ void cp16(uint32_t dst, const void* src) {
    asm volatile("cp.async.cg.shared.global [%0], [%1], 16;"
                 :: "r"(dst), "l"(src));
}
__device__ __forceinline__ void cp_commit() {
    asm volatile("cp.async.commit_group;");
}
// bulk DMA: global -> shared, completion via mbarrier complete_tx
__device__ __forceinline__ void cpbulk(uint32_t dst, const void* src,
                                       uint32_t bytes, uint32_t mbar) {
    asm volatile(
        "cp.async.bulk.shared::cluster.global.mbarrier::complete_tx::bytes "
        "[%0], [%1], %2, [%3];"
        :: "r"(dst), "l"(src), "r"(bytes), "r"(mbar) : "memory");
}
#define MBAR_INIT(mb, n) \
    asm volatile("mbarrier.init.shared.b64 [%0], %1;" \
                 :: "r"(mb), "r"((uint32_t)(n)) : "memory")
#define MBAR_EXPECT_TX(mb, bytes) \
    asm volatile("mbarrier.arrive.expect_tx.shared.b64 _, [%0], %1;" \
                 :: "r"(mb), "r"((uint32_t)(bytes)) : "memory")
__device__ __forceinline__ void mbar_wait(uint32_t mb, uint32_t parity) {
    asm volatile(
        "{\n\t.reg .pred P;\n\t"
        "W%=:\n\t"
        "mbarrier.try_wait.parity.acquire.cta.shared::cta.b64 P, [%0], %1, 0x989680;\n\t"
        "@P bra.uni D%=;\n\t"
        "bra.uni W%=;\n\t"
        "D%=:\n\t}"
        :: "r"(mb), "r"(parity) : "memory");
}
__device__ __forceinline__ void ldsm4(uint32_t* r, uint32_t addr) {
    asm volatile("ldmatrix.sync.aligned.m8n8.x4.shared.b16 {%0,%1,%2,%3}, [%4];"
                 : "=r"(r[0]), "=r"(r[1]), "=r"(r[2]), "=r"(r[3]) : "r"(addr));
}
__device__ __forceinline__ void mma_bf16v(float* c, const uint32_t* a,
                                          const uint32_t* b) {
    asm volatile(
        "mma.sync.aligned.m16n8k16.row.col.f32.bf16.bf16.f32 "
        "{%0,%1,%2,%3}, {%4,%5,%6,%7}, {%8,%9}, {%0,%1,%2,%3};"
        : "+f"(c[0]), "+f"(c[1]), "+f"(c[2]), "+f"(c[3])
        : "r"(a[0]), "r"(a[1]), "r"(a[2]), "r"(a[3]), "r"(b[0]), "r"(b[1]));
}
__device__ __forceinline__ uint32_t pack_bf16(float x, float y) {
    __nv_bfloat162 v = __floats2bfloat162_rn(x, y);
    return *(uint32_t*)&v;
}

// ---------------------------------------------------------------------------
// fp32 -> bf16 hi/lo split (elementwise, grid-stride, n % 4 == 0)
// ---------------------------------------------------------------------------
__global__ void conv_split_kernel(const float* __restrict__ in,
                                  __nv_bfloat16* __restrict__ hi,
                                  __nv_bfloat16* __restrict__ lo, int n)
{
    int stride = gridDim.x * blockDim.x * 4;
    for (int i = (blockIdx.x * blockDim.x + threadIdx.x) * 4; i < n; i += stride) {
        float4 f = *(const float4*)&in[i];
        __nv_bfloat16 hx = __float2bfloat16(f.x);
        __nv_bfloat16 hy = __float2bfloat16(f.y);
        __nv_bfloat16 hz = __float2bfloat16(f.z);
        __nv_bfloat16 hw = __float2bfloat16(f.w);
        uint32_t h0 = pack_bf16(f.x, f.y);
        uint32_t h1 = pack_bf16(f.z, f.w);
        uint32_t l0 = pack_bf16(f.x - __bfloat162float(hx), f.y - __bfloat162float(hy));
        uint32_t l1 = pack_bf16(f.z - __bfloat162float(hz), f.w - __bfloat162float(hw));
        *(uint2*)&hi[i] = make_uint2(h0, h1);
        *(uint2*)&lo[i] = make_uint2(l0, l1);
    }
}

// ---------------------------------------------------------------------------
// HMMA pre-GEMM (R9 known-good, 128x64): C = Ah@(Wh+Wl)^T + Al@Wh^T + bias
// ---------------------------------------------------------------------------
#define PRS 80
#define P_AHI 0
#define P_ALO 10240
#define P_BHI 20480
#define P_BLO 25600
#define P_STAGE 30720
#define P_SMEM (2 * P_STAGE)

__global__ __launch_bounds__(256) void hmma_pre_gemm(
    const __nv_bfloat16* __restrict__ Ahi,
    const __nv_bfloat16* __restrict__ Alo,
    const __nv_bfloat16* __restrict__ Whi,
    const __nv_bfloat16* __restrict__ Wlo,
    const float* __restrict__ b0,
    const float* __restrict__ b1,
    float* __restrict__ C,
    int K)
{
    extern __shared__ char smb[];
    const uint32_t smu = smem_u32(smb);
    const int tid  = threadIdx.x;
    const int lane = tid & 31;
    const int wid  = tid >> 5;
    const int wm   = wid >> 1;
    const int wn   = wid & 1;
    const int brow = blockIdx.y * 128;
    const int bcol = blockIdx.x * 64;

    float acc[2][4][4];
#pragma unroll
    for (int mi = 0; mi < 2; mi++)
#pragma unroll
        for (int nj = 0; nj < 4; nj++)
#pragma unroll
            for (int q = 0; q < 4; q++) acc[mi][nj][q] = 0.f;

    const int grp = lane >> 3, rin = lane & 7;
    const uint32_t a_off = (uint32_t)((wm * 32 + (grp & 1) * 8 + rin) * PRS
                                      + (grp >> 1) * 16);
    const uint32_t b_off = (uint32_t)((wn * 32 + (grp >> 1) * 8 + rin) * PRS
                                      + (grp & 1) * 16);

    const int KT = K >> 5;

    auto issue_stage = [&](int kt) {
        const uint32_t sb = smu + (uint32_t)((kt & 1) * P_STAGE);
        const int k0 = kt * 32;
#pragma unroll
        for (int i = 0; i < 6; i++) {
            int u = tid + i * 256;
            if (u < 1024) {
                int plane = u >> 9, idx = u & 511;
                int row = idx >> 2, seg = idx & 3;
                const __nv_bfloat16* src = (plane ? Alo : Ahi)
                    + (size_t)(brow + row) * K + k0 + seg * 8;
                cp16(sb + P_AHI + (uint32_t)(plane * 10240 + row * PRS + seg * 16), src);
            } else {
                int v = u - 1024;
                int plane = v >> 8, idx = v & 255;
                int row = idx >> 2, seg = idx & 3;
                const __nv_bfloat16* src = (plane ? Wlo : Whi)
                    + (size_t)(bcol + row) * K + k0 + seg * 8;
                cp16(sb + P_BHI + (uint32_t)(plane * 5120 + row * PRS + seg * 16), src);
            }
        }
        cp_commit();
    };

    issue_stage(0);
    for (int kt = 0; kt < KT; kt++) {
        if (kt + 1 < KT) {
            issue_stage(kt + 1);
            asm volatile("cp.async.wait_group 1;");
        } else {
            asm volatile("cp.async.wait_group 0;");
        }
        __syncthreads();
        const uint32_t sb = smu + (uint32_t)((kt & 1) * P_STAGE);
#pragma unroll
        for (int s = 0; s < 2; s++) {
            uint32_t ah[2][4], al[2][4], bh[2][4], bl[2][4];
#pragma unroll
            for (int mi = 0; mi < 2; mi++) {
                ldsm4(ah[mi], sb + P_AHI + a_off + (uint32_t)(mi * 16 * PRS + s * 32));
                ldsm4(al[mi], sb + P_ALO + a_off + (uint32_t)(mi * 16 * PRS + s * 32));
            }
#pragma unroll
            for (int nh = 0; nh < 2; nh++) {
                ldsm4(bh[nh], sb + P_BHI + b_off + (uint32_t)(nh * 16 * PRS + s * 32));
                ldsm4(bl[nh], sb + P_BLO + b_off + (uint32_t)(nh * 16 * PRS + s * 32));
            }
#pragma unroll
            for (int mi = 0; mi < 2; mi++)
#pragma unroll
                for (int nj = 0; nj < 4; nj++) {
                    const uint32_t* bhf = &bh[nj >> 1][(nj & 1) * 2];
                    const uint32_t* blf = &bl[nj >> 1][(nj & 1) * 2];
                    mma_bf16v(acc[mi][nj], ah[mi], bhf);
                    mma_bf16v(acc[mi][nj], ah[mi], blf);
                    mma_bf16v(acc[mi][nj], al[mi], bhf);
                }
        }
        __syncthreads();
    }

    const int gid = lane >> 2, tig = lane & 3;
#pragma unroll
    for (int mi = 0; mi < 2; mi++) {
        const int r0 = brow + wm * 32 + mi * 16 + gid;
#pragma unroll
        for (int nj = 0; nj < 4; nj++) {
            const int col = bcol + wn * 32 + nj * 8 + tig * 2;
            float bx = b0[col] + b1[col];
            float by = b0[col + 1] + b1[col + 1];
            *(float2*)&C[(size_t)r0 * HH + col] =
                make_float2(acc[mi][nj][0] + bx, acc[mi][nj][1] + by);
            *(float2*)&C[(size_t)(r0 + 8) * HH + col] =
                make_float2(acc[mi][nj][2] + bx, acc[mi][nj][3] + by);
        }
    }
}

// ---------------------------------------------------------------------------
// Persistent HMMA recurrent layer — R9 structure with bulk-DMA staging.
// Per step: tid0 issues ~49 cp.async.bulk copies (chunk0+pre -> mbar0,
// chunk1 -> mbar1); all threads mbarrier-wait; MMA chunk0 overlaps chunk1 DMA.
// ---------------------------------------------------------------------------
__global__ __launch_bounds__(NTHR, 1) void rnn_layer_tc(
    const float* __restrict__ pre,
    float* __restrict__ hbase,
    const float* __restrict__ Whh)
{
    extern __shared__ char smb[];
    __shared__ uint64_t s_mbar[2];
    const uint32_t smu = smem_u32(smb);
    const uint32_t mb0 = smem_u32(&s_mbar[0]);
    const uint32_t mb1 = smem_u32(&s_mbar[1]);

    const int tid  = threadIdx.x;
    const int wid  = tid >> 5;
    const int lane = tid & 31;
    const int cb   = blockIdx.x & (NCOLBLK - 1);
    const int rg   = blockIdx.x >> 5;            // row group 0..3
    const int bcol = cb * NCOLS;
    const int brow = rg * NROWS;

    if (tid == 0) {
        MBAR_INIT(mb0, 1);
        MBAR_INIT(mb1, 1);
    }

    // one-time W slice: fp32 -> bf16 hi/lo, [n][k] padded rows
    for (int i = tid; i < NCOLS * HH; i += NTHR) {
        int n = i >> 10;
        int k = i & 1023;
        float v = Whh[(size_t)(bcol + n) * HH + k];
        __nv_bfloat16 hi = __float2bfloat16(v);
        __nv_bfloat16 lo = __float2bfloat16(v - __bfloat162float(hi));
        *(__nv_bfloat16*)(smb + SM_WHI + n * WROWB + k * 2) = hi;
        *(__nv_bfloat16*)(smb + SM_WLO + n * WROWB + k * 2) = lo;
    }
    __syncthreads();

    const int nt = wid & 3;             // n-tile (8 cols)
    const int kg = wid >> 2;            // k-group (half of each chunk)

    const int grp = lane >> 3;
    const int rin = lane & 7;
    const uint32_t a_lane_off =
        (uint32_t)(((grp & 1) * 8 + rin) * CROWB + (grp >> 1) * 16);
    const uint32_t b4_off =
        (uint32_t)((nt * 8 + rin) * WROWB + grp * 16);

    const size_t row_stride = (size_t)TT * HH;
    const uint32_t scr = smu + SM_SCR + (uint32_t)((nt * 32 + lane) * 16);

    for (int t = 0; t < TT; t++) {
        float acc[6][4];
#pragma unroll
        for (int i = 0; i < 6; i++)
#pragma unroll
            for (int q = 0; q < 4; q++) acc[i][q] = 0.f;

        if (t > 0) {
            const uint32_t par = (uint32_t)((t - 1) & 1);

            // ---- tid0 launches all DMA for this step ----
            if (tid == 0) {
                MBAR_EXPECT_TX(mb0, 32768u + 2048u);   // chunk0 hi+lo + pre
#pragma unroll
                for (int r = 0; r < NROWS; r++) {
                    const size_t gro = (size_t)(brow + r) * HH;
                    cpbulk(smu + SM_A0 + (uint32_t)(r * CROWB),
                           g_hhi + gro, 1024u, mb0);
                    cpbulk(smu + SM_A0 + CPLANE + (uint32_t)(r * CROWB),
                           g_hlo + gro, 1024u, mb0);
                    cpbulk(smu + SM_PRE + (uint32_t)(r * 128),
                           &pre[(size_t)(brow + r) * row_stride
                                + (size_t)t * HH + bcol], 128u, mb0);
                }
                MBAR_EXPECT_TX(mb1, 32768u);           // chunk1 hi+lo
#pragma unroll
                for (int r = 0; r < NROWS; r++) {
                    const size_t gro = (size_t)(brow + r) * HH + 512;
                    cpbulk(smu + SM_A1 + (uint32_t)(r * CROWB),
                           g_hhi + gro, 1024u, mb1);
                    cpbulk(smu + SM_A1 + CPLANE + (uint32_t)(r * CROWB),
                           g_hlo + gro, 1024u, mb1);
                }
            }

            // ---- MMA chunk 0 (after mbar0), then chunk 1 (after mbar1) ----
#pragma unroll
            for (int c = 0; c < 2; c++) {
                mbar_wait(c ? mb1 : mb0, par);
                const uint32_t ab = smu + (c ? SM_A1 : SM_A0) + a_lane_off
                                  + (uint32_t)(kg * 512);
                const uint32_t bb_hi = smu + SM_WHI + b4_off
                                     + (uint32_t)(c * 1024 + kg * 512);
                const uint32_t bb_lo = smu + SM_WLO + b4_off
                                     + (uint32_t)(c * 1024 + kg * 512);
#pragma unroll
                for (int p2 = 0; p2 < 8; p2++) {      // k32 groups
                    uint32_t bh[4], bl[4];
                    ldsm4(bh, bb_hi + p2 * 64);
                    ldsm4(bl, bb_lo + p2 * 64);
#pragma unroll
                    for (int e = 0; e < 2; e++) {
                        const int s = p2 * 2 + e;
                        uint32_t ah[4], al[4];
                        ldsm4(ah, ab + s * 32);
                        ldsm4(al, ab + CPLANE + s * 32);
                        const uint32_t* bhf = &bh[e * 2];
                        const uint32_t* blf = &bl[e * 2];
                        mma_bf16v(acc[(s & 1) * 3 + 0], ah, bhf);
                        mma_bf16v(acc[(s & 1) * 3 + 1], ah, blf);
                        mma_bf16v(acc[(s & 1) * 3 + 2], al, bhf);
                    }
                }
            }
        } else {
            // t == 0: just prefetch the pre tile (cp.async, one-time)
            if (tid < 128) {
                int row = tid >> 3, q = tid & 7;
                cp16(smu + SM_PRE + (uint32_t)(row * 128 + q * 16),
                     &pre[(size_t)(brow + row) * row_stride + bcol + q * 4]);
            }
            cp_commit();
            asm volatile("cp.async.wait_group 0;");
            __syncthreads();
        }

        // ---- merge k-group partials ----
        float c0 = 0.f, c1 = 0.f, c2 = 0.f, c3 = 0.f;
#pragma unroll
        for (int i = 0; i < 6; i++) {
            c0 += acc[i][0]; c1 += acc[i][1];
            c2 += acc[i][2]; c3 += acc[i][3];
        }
        if (t > 0) {
            if (kg == 1) {
                asm volatile("st.shared.v4.f32 [%0], {%1,%2,%3,%4};"
                             :: "r"(scr), "f"(c0), "f"(c1), "f"(c2), "f"(c3)
                             : "memory");
            }
            __syncthreads();
        }

        // ---- epilogue (kg==0 warps): h = tanh(pre + acc) ----
        const int gid = lane >> 2;
        const int tig = lane & 3;
        const int m0 = brow + gid;
        const int m1 = m0 + 8;
        const int nc = bcol + nt * 8 + tig * 2;
        float h00, h01, h10, h11;

        if (kg == 0) {
            if (t > 0) {
                float s0, s1, s2, s3;
                asm volatile("ld.shared.v4.f32 {%0,%1,%2,%3}, [%4];"
                             : "=f"(s0), "=f"(s1), "=f"(s2), "=f"(s3) : "r"(scr));
                c0 += s0; c1 += s1; c2 += s2; c3 += s3;
            }
            const uint32_t pofs = (uint32_t)((nt * 8 + tig * 2) * 4);
            float2 p0 = *(const float2*)(smb + SM_PRE + gid * 128 + pofs);
            float2 p1 = *(const float2*)(smb + SM_PRE + (gid + 8) * 128 + pofs);
            h00 = tanhf(p0.x + c0);
            h01 = tanhf(p0.y + c1);
            h10 = tanhf(p1.x + c2);
            h11 = tanhf(p1.y + c3);

            __nv_bfloat16 e00 = __float2bfloat16(h00);
            __nv_bfloat16 e01 = __float2bfloat16(h01);
            __nv_bfloat16 e10 = __float2bfloat16(h10);
            __nv_bfloat16 e11 = __float2bfloat16(h11);
            *(uint32_t*)&g_hhi[(size_t)m0 * HH + nc] = pack_bf16(h00, h01);
            *(uint32_t*)&g_hhi[(size_t)m1 * HH + nc] = pack_bf16(h10, h11);
            *(uint32_t*)&g_hlo[(size_t)m0 * HH + nc] =
                pack_bf16(h00 - __bfloat162float(e00), h01 - __bfloat162float(e01));
            *(uint32_t*)&g_hlo[(size_t)m1 * HH + nc] =
                pack_bf16(h10 - __bfloat162float(e10), h11 - __bfloat162float(e11));
        }

        // ---- barrier: arrive early, drain off-path stores in spin window ----
        __syncthreads();
        __threadfence();
        unsigned int mygen = 0;
        if (tid == 0) {
            mygen = g_bar_gen[rg];
            unsigned int tkt = atomicAdd(&g_bar_count[rg], 1u);
            if (tkt == NCOLBLK - 1) {
                g_bar_count[rg] = 0;
                __threadfence();
                g_bar_gen[rg] = mygen + 1;
            }
        }
        if (kg == 0) {
            const size_t o0 = (size_t)m0 * row_stride + (size_t)t * HH + nc;
            const size_t o1 = (size_t)m1 * row_stride + (size_t)t * HH + nc;
            *(float2*)&hbase[o0] = make_float2(h00, h01);
            *(float2*)&hbase[o1] = make_float2(h10, h11);
        }
        if (tid == 0) {
            while (g_bar_gen[rg] == mygen) { }
        }
        __syncthreads();
    }
}

// ---------------------------------------------------------------------------
__global__ void finalize_kernel(float* __restrict__ out)
{
    int i = blockIdx.x * blockDim.x + threadIdx.x;   // over B*H
    if (i >= BB * HH) return;
    int b = i / HH;
    int h = i - b * HH;
    float* hfin = out + (size_t)BB * TT * HH;
    size_t src = (size_t)b * TT * HH + (size_t)(TT - 1) * HH + h;
    hfin[i] = g_buf0[src];
    hfin[(size_t)BB * HH + i] = out[src];
}

// ---------------------------------------------------------------------------

extern "C" void kernel_launch(void* const* d_in, const int* in_sizes, int n_in,
                              void* d_out, int out_size)
{
    const float* x      = (const float*)d_in[0];
    const float* W_ih0  = (const float*)d_in[1];
    const float* W_hh0  = (const float*)d_in[2];
    const float* b_ih0  = (const float*)d_in[3];
    const float* b_hh0  = (const float*)d_in[4];
    const float* W_ih1  = (const float*)d_in[5];
    const float* W_hh1  = (const float*)d_in[6];
    const float* b_ih1  = (const float*)d_in[7];
    const float* b_hh1  = (const float*)d_in[8];
    float* out = (float*)d_out;

    void* p;
    cudaGetSymbolAddress(&p, g_buf0); float* buf0 = (float*)p;
    cudaGetSymbolAddress(&p, g_buf1); float* buf1 = (float*)p;
    cudaGetSymbolAddress(&p, g_ahi);  __nv_bfloat16* ahi = (__nv_bfloat16*)p;
    cudaGetSymbolAddress(&p, g_alo);  __nv_bfloat16* alo = (__nv_bfloat16*)p;
    cudaGetSymbolAddress(&p, g_whi);  __nv_bfloat16* whi = (__nv_bfloat16*)p;
    cudaGetSymbolAddress(&p, g_wlo);  __nv_bfloat16* wlo = (__nv_bfloat16*)p;

    cudaFuncSetAttribute(rnn_layer_tc,
                         cudaFuncAttributeMaxDynamicSharedMemorySize, SM_TOTAL);
    cudaFuncSetAttribute(hmma_pre_gemm,
                         cudaFuncAttributeMaxDynamicSharedMemorySize, P_SMEM);

    // 1) split X and W_ih0 to bf16 hi/lo
    conv_split_kernel<<<1024, 256>>>(x, ahi, alo, BB * TT * DIN);
    conv_split_kernel<<<256, 256>>>(W_ih0, whi, wlo, HH * DIN);

    // 2) pre0 = X @ W_ih0^T + b_ih0 + b_hh0
    {
        dim3 grid(HH / 64, (BB * TT) / 128);
        hmma_pre_gemm<<<grid, 256, P_SMEM>>>(ahi, alo, whi, wlo,
                                             b_ih0, b_hh0, buf0, DIN);
    }

    // 3) layer-0 recurrence (in place over buf0)
    rnn_layer_tc<<<RNBLK, NTHR, SM_TOTAL>>>(buf0, buf0, W_hh0);

    // 4) split H0 and W_ih1, then pre1 = H0 @ W_ih1^T + b_ih1 + b_hh1
    conv_split_kernel<<<1024, 256>>>(buf0, ahi, alo, BB * TT * HH);
    conv_split_kernel<<<512, 256>>>(W_ih1, whi, wlo, HH * HH);
    {
        dim3 grid(HH / 64, (BB * TT) / 128);
        hmma_pre_gemm<<<grid, 256, P_SMEM>>>(ahi, alo, whi, wlo,
                                             b_ih1, b_hh1, buf1, HH);
    }

    // 5) layer-1 recurrence (writes h1 into outputs region)
    rnn_layer_tc<<<RNBLK, NTHR, SM_TOTAL>>>(buf1, out, W_hh1);

    // 6) h_final
    finalize_kernel<<<(BB * HH + 255) / 256, 256>>>(out);
}

// round 15
// speedup vs baseline: 1.1248x; 1.1248x over previous
#include <cuda_runtime.h>
#include <cuda_bf16.h>
#include <math.h>
#include <stdint.h>

#define BB 64
#define TT 512
#define DIN 512
#define HH 1024

// rnn grid: 32 col-groups x 4 row-groups = 128 blocks
#define NCOLBLK 32
#define NROWGRP 4
#define RNBLK (NCOLBLK * NROWGRP)
#define NCOLS 32     // hidden cols per block
#define NROWS 16     // batch rows per block
#define NTHR 256

// rnn SMEM layout (bytes; 16B-aligned)
#define WROWB 2064                 // W row stride: 1024 bf16 + 8 pad
#define CROWB 1040                 // A chunk row stride: 512 bf16 + 8 pad
#define CPLANE (NROWS * CROWB)     // 16640 (one hi or lo plane of a chunk)
#define CBUF (2 * CPLANE)          // 33280 (hi+lo)
#define SM_WHI 0
#define SM_WLO (NCOLS * WROWB)     // 66048
#define SM_A0  (2 * NCOLS * WROWB) // 132096
#define SM_A1  (SM_A0 + CBUF)      // 165376
#define SM_PRE (SM_A1 + CBUF)      // 198656 (16x32 fp32 pre tile)
#define SM_SCR (SM_PRE + 2048)     // 200704 (fp32 partial-C scratch)
#define SM_TOTAL (SM_SCR + 2048)   // 202752

// Scratch: buf0 holds pre0 then h0 in place; buf1 holds pre1. h1 -> d_out.
__device__ float g_buf0[(size_t)BB * TT * HH];
__device__ float g_buf1[(size_t)BB * TT * HH];
// Current h(t) as bf16 hi/lo split (rewritten every step)
__device__ __nv_bfloat16 g_hhi[(size_t)BB * HH];
__device__ __nv_bfloat16 g_hlo[(size_t)BB * HH];
// bf16 hi/lo split of the big GEMM A operand (X, then H0) and W operand
__device__ __nv_bfloat16 g_ahi[(size_t)BB * TT * HH];
__device__ __nv_bfloat16 g_alo[(size_t)BB * TT * HH];
__device__ __nv_bfloat16 g_whi[(size_t)HH * HH];
__device__ __nv_bfloat16 g_wlo[(size_t)HH * HH];

// Per-row-group grid barriers (32 arrivals each; generation-based)
__device__ unsigned int          g_bar_count[NROWGRP];
__device__ volatile unsigned int g_bar_gen[NROWGRP];

// ---------------------- PTX helpers (sm_80+ features only) ----------------
__device__ __forceinline__ uint32_t smem_u32(const void* p) {
    uint32_t a;
    asm("{ .reg .u64 t; cvta.to.shared.u64 t, %1; cvt.u32.u64 %0, t; }"
        : "=r"(a) : "l"(p));
    return a;
}
__device__ __forceinline__ void cp16(uint32_t dst, const void* src) {
    asm volatile("cp.async.cg.shared.global [%0], [%1], 16;"
                 :: "r"(dst), "l"(src));
}
__device__ __forceinline__ void cp_commit() {
    asm volatile("cp.async.commit_group;");
}
__device__ __forceinline__ void ldsm4(uint32_t* r, uint32_t addr) {
    asm volatile("ldmatrix.sync.aligned.m8n8.x4.shared.b16 {%0,%1,%2,%3}, [%4];"
                 : "=r"(r[0]), "=r"(r[1]), "=r"(r[2]), "=r"(r[3]) : "r"(addr));
}
__device__ __forceinline__ void mma_bf16v(float* c, const uint32_t* a,
                                          const uint32_t* b) {
    asm volatile(
        "mma.sync.aligned.m16n8k16.row.col.f32.bf16.bf16.f32 "
        "{%0,%1,%2,%3}, {%4,%5,%6,%7}, {%8,%9}, {%0,%1,%2,%3};"
        : "+f"(c[0]), "+f"(c[1]), "+f"(c[2]), "+f"(c[3])
        : "r"(a[0]), "r"(a[1]), "r"(a[2]), "r"(a[3]), "r"(b[0]), "r"(b[1]));
}
__device__ __forceinline__ uint32_t pack_bf16(float x, float y) {
    __nv_bfloat162 v = __floats2bfloat162_rn(x, y);
    return *(uint32_t*)&v;
}
// release-arrive / acquire-poll barrier primitives (gpu scope)
__device__ __forceinline__ uint32_t atom_add_release(unsigned int* p) {
    uint32_t old;
    asm volatile("atom.release.gpu.global.add.u32 %0, [%1], 1;"
                 : "=r"(old) : "l"(p) : "memory");
    return old;
}
__device__ __forceinline__ void st_release(volatile unsigned int* p, uint32_t v) {
    asm volatile("st.release.gpu.global.u32 [%0], %1;"
                 :: "l"((unsigned int*)p), "r"(v) : "memory");
}
__device__ __forceinline__ uint32_t ld_acquire(volatile unsigned int* p) {
    uint32_t v;
    asm volatile("ld.acquire.gpu.global.u32 %0, [%1];"
                 : "=r"(v) : "l"((const unsigned int*)p) : "memory");
    return v;
}

// ---------------------------------------------------------------------------
// fp32 -> bf16 hi/lo split (elementwise, grid-stride, n % 4 == 0)
// ---------------------------------------------------------------------------
__global__ void conv_split_kernel(const float* __restrict__ in,
                                  __nv_bfloat16* __restrict__ hi,
                                  __nv_bfloat16* __restrict__ lo, int n)
{
    int stride = gridDim.x * blockDim.x * 4;
    for (int i = (blockIdx.x * blockDim.x + threadIdx.x) * 4; i < n; i += stride) {
        float4 f = *(const float4*)&in[i];
        __nv_bfloat16 hx = __float2bfloat16(f.x);
        __nv_bfloat16 hy = __float2bfloat16(f.y);
        __nv_bfloat16 hz = __float2bfloat16(f.z);
        __nv_bfloat16 hw = __float2bfloat16(f.w);
        uint32_t h0 = pack_bf16(f.x, f.y);
        uint32_t h1 = pack_bf16(f.z, f.w);
        uint32_t l0 = pack_bf16(f.x - __bfloat162float(hx), f.y - __bfloat162float(hy));
        uint32_t l1 = pack_bf16(f.z - __bfloat162float(hz), f.w - __bfloat162float(hw));
        *(uint2*)&hi[i] = make_uint2(h0, h1);
        *(uint2*)&lo[i] = make_uint2(l0, l1);
    }
}

// ---------------------------------------------------------------------------
// HMMA pre-GEMM (R9 known-good, 128x64): C = Ah@(Wh+Wl)^T + Al@Wh^T + bias
// ---------------------------------------------------------------------------
#define PRS 80
#define P_AHI 0
#define P_ALO 10240
#define P_BHI 20480
#define P_BLO 25600
#define P_STAGE 30720
#define P_SMEM (2 * P_STAGE)

__global__ __launch_bounds__(256) void hmma_pre_gemm(
    const __nv_bfloat16* __restrict__ Ahi,
    const __nv_bfloat16* __restrict__ Alo,
    const __nv_bfloat16* __restrict__ Whi,
    const __nv_bfloat16* __restrict__ Wlo,
    const float* __restrict__ b0,
    const float* __restrict__ b1,
    float* __restrict__ C,
    int K)
{
    extern __shared__ char smb[];
    const uint32_t smu = smem_u32(smb);
    const int tid  = threadIdx.x;
    const int lane = tid & 31;
    const int wid  = tid >> 5;
    const int wm   = wid >> 1;
    const int wn   = wid & 1;
    const int brow = blockIdx.y * 128;
    const int bcol = blockIdx.x * 64;

    float acc[2][4][4];
#pragma unroll
    for (int mi = 0; mi < 2; mi++)
#pragma unroll
        for (int nj = 0; nj < 4; nj++)
#pragma unroll
            for (int q = 0; q < 4; q++) acc[mi][nj][q] = 0.f;

    const int grp = lane >> 3, rin = lane & 7;
    const uint32_t a_off = (uint32_t)((wm * 32 + (grp & 1) * 8 + rin) * PRS
                                      + (grp >> 1) * 16);
    const uint32_t b_off = (uint32_t)((wn * 32 + (grp >> 1) * 8 + rin) * PRS
                                      + (grp & 1) * 16);

    const int KT = K >> 5;

    auto issue_stage = [&](int kt) {
        const uint32_t sb = smu + (uint32_t)((kt & 1) * P_STAGE);
        const int k0 = kt * 32;
#pragma unroll
        for (int i = 0; i < 6; i++) {
            int u = tid + i * 256;
            if (u < 1024) {
                int plane = u >> 9, idx = u & 511;
                int row = idx >> 2, seg = idx & 3;
                const __nv_bfloat16* src = (plane ? Alo : Ahi)
                    + (size_t)(brow + row) * K + k0 + seg * 8;
                cp16(sb + P_AHI + (uint32_t)(plane * 10240 + row * PRS + seg * 16), src);
            } else {
                int v = u - 1024;
                int plane = v >> 8, idx = v & 255;
                int row = idx >> 2, seg = idx & 3;
                const __nv_bfloat16* src = (plane ? Wlo : Whi)
                    + (size_t)(bcol + row) * K + k0 + seg * 8;
                cp16(sb + P_BHI + (uint32_t)(plane * 5120 + row * PRS + seg * 16), src);
            }
        }
        cp_commit();
    };

    issue_stage(0);
    for (int kt = 0; kt < KT; kt++) {
        if (kt + 1 < KT) {
            issue_stage(kt + 1);
            asm volatile("cp.async.wait_group 1;");
        } else {
            asm volatile("cp.async.wait_group 0;");
        }
        __syncthreads();
        const uint32_t sb = smu + (uint32_t)((kt & 1) * P_STAGE);
#pragma unroll
        for (int s = 0; s < 2; s++) {
            uint32_t ah[2][4], al[2][4], bh[2][4], bl[2][4];
#pragma unroll
            for (int mi = 0; mi < 2; mi++) {
                ldsm4(ah[mi], sb + P_AHI + a_off + (uint32_t)(mi * 16 * PRS + s * 32));
                ldsm4(al[mi], sb + P_ALO + a_off + (uint32_t)(mi * 16 * PRS + s * 32));
            }
#pragma unroll
            for (int nh = 0; nh < 2; nh++) {
                ldsm4(bh[nh], sb + P_BHI + b_off + (uint32_t)(nh * 16 * PRS + s * 32));
                ldsm4(bl[nh], sb + P_BLO + b_off + (uint32_t)(nh * 16 * PRS + s * 32));
            }
#pragma unroll
            for (int mi = 0; mi < 2; mi++)
#pragma unroll
                for (int nj = 0; nj < 4; nj++) {
                    const uint32_t* bhf = &bh[nj >> 1][(nj & 1) * 2];
                    const uint32_t* blf = &bl[nj >> 1][(nj & 1) * 2];
                    mma_bf16v(acc[mi][nj], ah[mi], bhf);
                    mma_bf16v(acc[mi][nj], ah[mi], blf);
                    mma_bf16v(acc[mi][nj], al[mi], bhf);
                }
        }
        __syncthreads();
    }

    const int gid = lane >> 2, tig = lane & 3;
#pragma unroll
    for (int mi = 0; mi < 2; mi++) {
        const int r0 = brow + wm * 32 + mi * 16 + gid;
#pragma unroll
        for (int nj = 0; nj < 4; nj++) {
            const int col = bcol + wn * 32 + nj * 8 + tig * 2;
            float bx = b0[col] + b1[col];
            float by = b0[col + 1] + b1[col + 1];
            *(float2*)&C[(size_t)r0 * HH + col] =
                make_float2(acc[mi][nj][0] + bx, acc[mi][nj][1] + by);
            *(float2*)&C[(size_t)(r0 + 8) * HH + col] =
                make_float2(acc[mi][nj][2] + bx, acc[mi][nj][3] + by);
        }
    }
}

// ---------------------------------------------------------------------------
// Persistent HMMA recurrent layer — R9 structure; barrier uses release-arrive
// (atom.release.gpu) + acquire-poll instead of full __threadfence.
// ---------------------------------------------------------------------------
__global__ __launch_bounds__(NTHR, 1) void rnn_layer_tc(
    const float* __restrict__ pre,
    float* __restrict__ hbase,
    const float* __restrict__ Whh)
{
    extern __shared__ char smb[];
    const uint32_t smu = smem_u32(smb);

    const int tid  = threadIdx.x;
    const int wid  = tid >> 5;
    const int lane = tid & 31;
    const int cb   = blockIdx.x & (NCOLBLK - 1);
    const int rg   = blockIdx.x >> 5;            // row group 0..3
    const int bcol = cb * NCOLS;
    const int brow = rg * NROWS;

    // one-time W slice: fp32 -> bf16 hi/lo, [n][k] padded rows
    for (int i = tid; i < NCOLS * HH; i += NTHR) {
        int n = i >> 10;
        int k = i & 1023;
        float v = Whh[(size_t)(bcol + n) * HH + k];
        __nv_bfloat16 hi = __float2bfloat16(v);
        __nv_bfloat16 lo = __float2bfloat16(v - __bfloat162float(hi));
        *(__nv_bfloat16*)(smb + SM_WHI + n * WROWB + k * 2) = hi;
        *(__nv_bfloat16*)(smb + SM_WLO + n * WROWB + k * 2) = lo;
    }
    __syncthreads();

    const int nt = wid & 3;             // n-tile (8 cols)
    const int kg = wid >> 2;            // k-group (half of each chunk)

    const int grp = lane >> 3;
    const int rin = lane & 7;
    const uint32_t a_lane_off =
        (uint32_t)(((grp & 1) * 8 + rin) * CROWB + (grp >> 1) * 16);
    const uint32_t b4_off =
        (uint32_t)((nt * 8 + rin) * WROWB + grp * 16);

    const size_t row_stride = (size_t)TT * HH;
    const uint32_t scr = smu + SM_SCR + (uint32_t)((nt * 32 + lane) * 16);

    for (int t = 0; t < TT; t++) {
        float acc[6][4];
#pragma unroll
        for (int i = 0; i < 6; i++)
#pragma unroll
            for (int q = 0; q < 4; q++) acc[i][q] = 0.f;

        if (t > 0) {
            // ---- stage chunk 0 (k 0..511, hi+lo) ----
#pragma unroll
            for (int i = 0; i < 8; i++) {
                int u = tid + i * NTHR;           // 0..2047
                int plane = u >> 10;
                int idx = u & 1023;
                int row = idx >> 6;
                int ku  = idx & 63;
                uint32_t d = smu + SM_A0 + (uint32_t)(plane * CPLANE + row * CROWB + ku * 16);
                const __nv_bfloat16* src = (plane ? g_hlo : g_hhi)
                    + (size_t)(brow + row) * HH + ku * 8;
                cp16(d, src);
            }
            cp_commit();

            // ---- stage chunk 1 (k 512..1023) + pre tile ----
#pragma unroll
            for (int i = 0; i < 8; i++) {
                int u = tid + i * NTHR;
                int plane = u >> 10;
                int idx = u & 1023;
                int row = idx >> 6;
                int ku  = idx & 63;
                uint32_t d = smu + SM_A1 + (uint32_t)(plane * CPLANE + row * CROWB + ku * 16);
                const __nv_bfloat16* src = (plane ? g_hlo : g_hhi)
                    + (size_t)(brow + row) * HH + 512 + ku * 8;
                cp16(d, src);
            }
            if (tid < 128) {
                int row = tid >> 3, q = tid & 7;
                cp16(smu + SM_PRE + (uint32_t)(row * 128 + q * 16),
                     &pre[(size_t)(brow + row) * row_stride + (size_t)t * HH
                          + bcol + q * 4]);
            }
            cp_commit();

            // ---- MMA chunk 0, then chunk 1 ----
            asm volatile("cp.async.wait_group 1;");
            __syncthreads();
#pragma unroll
            for (int c = 0; c < 2; c++) {
                if (c == 1) {
                    asm volatile("cp.async.wait_group 0;");
                    __syncthreads();
                }
                const uint32_t ab = smu + (c ? SM_A1 : SM_A0) + a_lane_off
                                  + (uint32_t)(kg * 512);
                const uint32_t bb_hi = smu + SM_WHI + b4_off
                                     + (uint32_t)(c * 1024 + kg * 512);
                const uint32_t bb_lo = smu + SM_WLO + b4_off
                                     + (uint32_t)(c * 1024 + kg * 512);
#pragma unroll
                for (int p2 = 0; p2 < 8; p2++) {      // k32 groups
                    uint32_t bh[4], bl[4];
                    ldsm4(bh, bb_hi + p2 * 64);
                    ldsm4(bl, bb_lo + p2 * 64);
#pragma unroll
                    for (int e = 0; e < 2; e++) {
                        const int s = p2 * 2 + e;
                        uint32_t ah[4], al[4];
                        ldsm4(ah, ab + s * 32);
                        ldsm4(al, ab + CPLANE + s * 32);
                        const uint32_t* bhf = &bh[e * 2];
                        const uint32_t* blf = &bl[e * 2];
                        mma_bf16v(acc[(s & 1) * 3 + 0], ah, bhf);
                        mma_bf16v(acc[(s & 1) * 3 + 1], ah, blf);
                        mma_bf16v(acc[(s & 1) * 3 + 2], al, bhf);
                    }
                }
            }
        } else {
            // t == 0: just prefetch the pre tile
            if (tid < 128) {
                int row = tid >> 3, q = tid & 7;
                cp16(smu + SM_PRE + (uint32_t)(row * 128 + q * 16),
                     &pre[(size_t)(brow + row) * row_stride + bcol + q * 4]);
            }
            cp_commit();
            asm volatile("cp.async.wait_group 0;");
            __syncthreads();
        }

        // ---- merge k-group partials ----
        float c0 = 0.f, c1 = 0.f, c2 = 0.f, c3 = 0.f;
#pragma unroll
        for (int i = 0; i < 6; i++) {
            c0 += acc[i][0]; c1 += acc[i][1];
            c2 += acc[i][2]; c3 += acc[i][3];
        }
        if (t > 0) {
            if (kg == 1) {
                asm volatile("st.shared.v4.f32 [%0], {%1,%2,%3,%4};"
                             :: "r"(scr), "f"(c0), "f"(c1), "f"(c2), "f"(c3)
                             : "memory");
            }
            __syncthreads();
        }

        // ---- epilogue (kg==0 warps): h = tanh(pre + acc) ----
        const int gid = lane >> 2;
        const int tig = lane & 3;
        const int m0 = brow + gid;
        const int m1 = m0 + 8;
        const int nc = bcol + nt * 8 + tig * 2;
        float h00, h01, h10, h11;

        if (kg == 0) {
            if (t > 0) {
                float s0, s1, s2, s3;
                asm volatile("ld.shared.v4.f32 {%0,%1,%2,%3}, [%4];"
                             : "=f"(s0), "=f"(s1), "=f"(s2), "=f"(s3) : "r"(scr));
                c0 += s0; c1 += s1; c2 += s2; c3 += s3;
            }
            const uint32_t pofs = (uint32_t)((nt * 8 + tig * 2) * 4);
            float2 p0 = *(const float2*)(smb + SM_PRE + gid * 128 + pofs);
            float2 p1 = *(const float2*)(smb + SM_PRE + (gid + 8) * 128 + pofs);
            h00 = tanhf(p0.x + c0);
            h01 = tanhf(p0.y + c1);
            h10 = tanhf(p1.x + c2);
            h11 = tanhf(p1.y + c3);

            // state for next step (what peer blocks need) — store FIRST
            __nv_bfloat16 e00 = __float2bfloat16(h00);
            __nv_bfloat16 e01 = __float2bfloat16(h01);
            __nv_bfloat16 e10 = __float2bfloat16(h10);
            __nv_bfloat16 e11 = __float2bfloat16(h11);
            *(uint32_t*)&g_hhi[(size_t)m0 * HH + nc] = pack_bf16(h00, h01);
            *(uint32_t*)&g_hhi[(size_t)m1 * HH + nc] = pack_bf16(h10, h11);
            *(uint32_t*)&g_hlo[(size_t)m0 * HH + nc] =
                pack_bf16(h00 - __bfloat162float(e00), h01 - __bfloat162float(e01));
            *(uint32_t*)&g_hlo[(size_t)m1 * HH + nc] =
                pack_bf16(h10 - __bfloat162float(e10), h11 - __bfloat162float(e11));
        }

        // ---- barrier: release-arrive, drain fp32 output in spin window ----
        __syncthreads();
        unsigned int mygen = 0;
        if (tid == 0) {
            mygen = g_bar_gen[rg];
            unsigned int tkt = atom_add_release(&g_bar_count[rg]);
            if (tkt == NCOLBLK - 1) {
                g_bar_count[rg] = 0;
                st_release(&g_bar_gen[rg], mygen + 1u);
            }
        }
        if (kg == 0) {
            const size_t o0 = (size_t)m0 * row_stride + (size_t)t * HH + nc;
            const size_t o1 = (size_t)m1 * row_stride + (size_t)t * HH + nc;
            *(float2*)&hbase[o0] = make_float2(h00, h01);
            *(float2*)&hbase[o1] = make_float2(h10, h11);
        }
        if (tid == 0) {
            while (ld_acquire(&g_bar_gen[rg]) == mygen) { }
        }
        __syncthreads();
    }
}

// ---------------------------------------------------------------------------
__global__ void finalize_kernel(float* __restrict__ out)
{
    int i = blockIdx.x * blockDim.x + threadIdx.x;   // over B*H
    if (i >= BB * HH) return;
    int b = i / HH;
    int h = i - b * HH;
    float* hfin = out + (size_t)BB * TT * HH;
    size_t src = (size_t)b * TT * HH + (size_t)(TT - 1) * HH + h;
    hfin[i] = g_buf0[src];
    hfin[(size_t)BB * HH + i] = out[src];
}

// ---------------------------------------------------------------------------

extern "C" void kernel_launch(void* const* d_in, const int* in_sizes, int n_in,
                              void* d_out, int out_size)
{
    const float* x      = (const float*)d_in[0];
    const float* W_ih0  = (const float*)d_in[1];
    const float* W_hh0  = (const float*)d_in[2];
    const float* b_ih0  = (const float*)d_in[3];
    const float* b_hh0  = (const float*)d_in[4];
    const float* W_ih1  = (const float*)d_in[5];
    const float* W_hh1  = (const float*)d_in[6];
    const float* b_ih1  = (const float*)d_in[7];
    const float* b_hh1  = (const float*)d_in[8];
    float* out = (float*)d_out;

    void* p;
    cudaGetSymbolAddress(&p, g_buf0); float* buf0 = (float*)p;
    cudaGetSymbolAddress(&p, g_buf1); float* buf1 = (float*)p;
    cudaGetSymbolAddress(&p, g_ahi);  __nv_bfloat16* ahi = (__nv_bfloat16*)p;
    cudaGetSymbolAddress(&p, g_alo);  __nv_bfloat16* alo = (__nv_bfloat16*)p;
    cudaGetSymbolAddress(&p, g_whi);  __nv_bfloat16* whi = (__nv_bfloat16*)p;
    cudaGetSymbolAddress(&p, g_wlo);  __nv_bfloat16* wlo = (__nv_bfloat16*)p;

    cudaFuncSetAttribute(rnn_layer_tc,
                         cudaFuncAttributeMaxDynamicSharedMemorySize, SM_TOTAL);
    cudaFuncSetAttribute(hmma_pre_gemm,
                         cudaFuncAttributeMaxDynamicSharedMemorySize, P_SMEM);

    // 1) split X and W_ih0 to bf16 hi/lo
    conv_split_kernel<<<1024, 256>>>(x, ahi, alo, BB * TT * DIN);
    conv_split_kernel<<<256, 256>>>(W_ih0, whi, wlo, HH * DIN);

    // 2) pre0 = X @ W_ih0^T + b_ih0 + b_hh0
    {
        dim3 grid(HH / 64, (BB * TT) / 128);
        hmma_pre_gemm<<<grid, 256, P_SMEM>>>(ahi, alo, whi, wlo,
                                             b_ih0, b_hh0, buf0, DIN);
    }

    // 3) layer-0 recurrence (in place over buf0)
    rnn_layer_tc<<<RNBLK, NTHR, SM_TOTAL>>>(buf0, buf0, W_hh0);

    // 4) split H0 and W_ih1, then pre1 = H0 @ W_ih1^T + b_ih1 + b_hh1
    conv_split_kernel<<<1024, 256>>>(buf0, ahi, alo, BB * TT * HH);
    conv_split_kernel<<<512, 256>>>(W_ih1, whi, wlo, HH * HH);
    {
        dim3 grid(HH / 64, (BB * TT) / 128);
        hmma_pre_gemm<<<grid, 256, P_SMEM>>>(ahi, alo, whi, wlo,
                                             b_ih1, b_hh1, buf1, HH);
    }

    // 5) layer-1 recurrence (writes h1 into outputs region)
    rnn_layer_tc<<<RNBLK, NTHR, SM_TOTAL>>>(buf1, out, W_hh1);

    // 6) h_final
    finalize_kernel<<<(BB * HH + 255) / 256, 256>>>(out);
}

// round 16
// speedup vs baseline: 1.2848x; 1.1423x over previous
#include <cuda_runtime.h>
#include <cuda_bf16.h>
#include <math.h>
#include <stdint.h>

#define BB 64
#define TT 512
#define DIN 512
#define HH 1024

// rnn grid: 32 col-groups x 4 row-groups = 128 blocks
#define NCOLBLK 32
#define NROWGRP 4
#define RNBLK (NCOLBLK * NROWGRP)
#define NCOLS 32     // hidden cols per block
#define NROWS 16     // batch rows per block
#define NTHR 256

// rnn SMEM layout (bytes; 16B-aligned)
#define WROWB 2064                 // W row stride: 1024 bf16 + 8 pad
#define CROWB 1040                 // A chunk row stride: 512 bf16 + 8 pad
#define CPLANE (NROWS * CROWB)     // 16640 (one hi or lo plane of a chunk)
#define CBUF (2 * CPLANE)          // 33280 (hi+lo)
#define SM_WHI 0
#define SM_WLO (NCOLS * WROWB)     // 66048
#define SM_A0  (2 * NCOLS * WROWB) // 132096
#define SM_A1  (SM_A0 + CBUF)      // 165376
#define SM_PRE (SM_A1 + CBUF)      // 198656 (16x32 fp32 pre tile)
#define SM_SCR (SM_PRE + 2048)     // 200704 (fp32 partial-C scratch)
#define SM_TOTAL (SM_SCR + 2048)   // 202752

// Scratch: buf0 holds pre0 then h0 in place; buf1 holds pre1. h1 -> d_out.
__device__ float g_buf0[(size_t)BB * TT * HH];
__device__ float g_buf1[(size_t)BB * TT * HH];
// Current h(t) as bf16 hi/lo split (rewritten every step)
__device__ __nv_bfloat16 g_hhi[(size_t)BB * HH];
__device__ __nv_bfloat16 g_hlo[(size_t)BB * HH];
// bf16 hi/lo split of the big GEMM A operand (X, then H0) and W operand
__device__ __nv_bfloat16 g_ahi[(size_t)BB * TT * HH];
__device__ __nv_bfloat16 g_alo[(size_t)BB * TT * HH];
__device__ __nv_bfloat16 g_whi[(size_t)HH * HH];
__device__ __nv_bfloat16 g_wlo[(size_t)HH * HH];

// Count-spin barriers: 8 domains (layer0: 0-3, layer1: 4-7), one per 128B line.
// Zeroed by the first conv_split launch of every kernel_launch invocation;
// monotone within a launch (target at step t = 32*(t+1)). Replay-safe.
__device__ unsigned int g_cnt[8 * 32];

// ---------------------- PTX helpers (sm_80+ features only) ----------------
__device__ __forceinline__ uint32_t smem_u32(const void* p) {
    uint32_t a;
    asm("{ .reg .u64 t; cvta.to.shared.u64 t, %1; cvt.u32.u64 %0, t; }"
        : "=r"(a) : "l"(p));
    return a;
}
__device__ __forceinline__ void cp16(uint32_t dst, const void* src) {
    asm volatile("cp.async.cg.shared.global [%0], [%1], 16;"
                 :: "r"(dst), "l"(src));
}
__device__ __forceinline__ void cp_commit() {
    asm volatile("cp.async.commit_group;");
}
__device__ __forceinline__ void ldsm4(uint32_t* r, uint32_t addr) {
    asm volatile("ldmatrix.sync.aligned.m8n8.x4.shared.b16 {%0,%1,%2,%3}, [%4];"
                 : "=r"(r[0]), "=r"(r[1]), "=r"(r[2]), "=r"(r[3]) : "r"(addr));
}
__device__ __forceinline__ void mma_bf16v(float* c, const uint32_t* a,
                                          const uint32_t* b) {
    asm volatile(
        "mma.sync.aligned.m16n8k16.row.col.f32.bf16.bf16.f32 "
        "{%0,%1,%2,%3}, {%4,%5,%6,%7}, {%8,%9}, {%0,%1,%2,%3};"
        : "+f"(c[0]), "+f"(c[1]), "+f"(c[2]), "+f"(c[3])
        : "r"(a[0]), "r"(a[1]), "r"(a[2]), "r"(a[3]), "r"(b[0]), "r"(b[1]));
}
__device__ __forceinline__ uint32_t pack_bf16(float x, float y) {
    __nv_bfloat162 v = __floats2bfloat162_rn(x, y);
    return *(uint32_t*)&v;
}
__device__ __forceinline__ void atom_add_release(unsigned int* p) {
    uint32_t old;
    asm volatile("atom.release.gpu.global.add.u32 %0, [%1], 1;"
                 : "=r"(old) : "l"(p) : "memory");
}
__device__ __forceinline__ uint32_t ld_acquire(const unsigned int* p) {
    uint32_t v;
    asm volatile("ld.acquire.gpu.global.u32 %0, [%1];"
                 : "=r"(v) : "l"(p) : "memory");
    return v;
}

// ---------------------------------------------------------------------------
// fp32 -> bf16 hi/lo split; zflag!=0: block 0 also zeroes the 8 barrier words
// ---------------------------------------------------------------------------
__global__ void conv_split_kernel(const float* __restrict__ in,
                                  __nv_bfloat16* __restrict__ hi,
                                  __nv_bfloat16* __restrict__ lo, int n,
                                  int zflag)
{
    if (zflag && blockIdx.x == 0 && threadIdx.x < 8)
        g_cnt[threadIdx.x * 32] = 0;

    int stride = gridDim.x * blockDim.x * 4;
    for (int i = (blockIdx.x * blockDim.x + threadIdx.x) * 4; i < n; i += stride) {
        float4 f = *(const float4*)&in[i];
        __nv_bfloat16 hx = __float2bfloat16(f.x);
        __nv_bfloat16 hy = __float2bfloat16(f.y);
        __nv_bfloat16 hz = __float2bfloat16(f.z);
        __nv_bfloat16 hw = __float2bfloat16(f.w);
        uint32_t h0 = pack_bf16(f.x, f.y);
        uint32_t h1 = pack_bf16(f.z, f.w);
        uint32_t l0 = pack_bf16(f.x - __bfloat162float(hx), f.y - __bfloat162float(hy));
        uint32_t l1 = pack_bf16(f.z - __bfloat162float(hz), f.w - __bfloat162float(hw));
        *(uint2*)&hi[i] = make_uint2(h0, h1);
        *(uint2*)&lo[i] = make_uint2(l0, l1);
    }
}

// ---------------------------------------------------------------------------
// HMMA pre-GEMM (R9 known-good, 128x64): C = Ah@(Wh+Wl)^T + Al@Wh^T + bias
// ---------------------------------------------------------------------------
#define PRS 80
#define P_AHI 0
#define P_ALO 10240
#define P_BHI 20480
#define P_BLO 25600
#define P_STAGE 30720
#define P_SMEM (2 * P_STAGE)

__global__ __launch_bounds__(256) void hmma_pre_gemm(
    const __nv_bfloat16* __restrict__ Ahi,
    const __nv_bfloat16* __restrict__ Alo,
    const __nv_bfloat16* __restrict__ Whi,
    const __nv_bfloat16* __restrict__ Wlo,
    const float* __restrict__ b0,
    const float* __restrict__ b1,
    float* __restrict__ C,
    int K)
{
    extern __shared__ char smb[];
    const uint32_t smu = smem_u32(smb);
    const int tid  = threadIdx.x;
    const int lane = tid & 31;
    const int wid  = tid >> 5;
    const int wm   = wid >> 1;
    const int wn   = wid & 1;
    const int brow = blockIdx.y * 128;
    const int bcol = blockIdx.x * 64;

    float acc[2][4][4];
#pragma unroll
    for (int mi = 0; mi < 2; mi++)
#pragma unroll
        for (int nj = 0; nj < 4; nj++)
#pragma unroll
            for (int q = 0; q < 4; q++) acc[mi][nj][q] = 0.f;

    const int grp = lane >> 3, rin = lane & 7;
    const uint32_t a_off = (uint32_t)((wm * 32 + (grp & 1) * 8 + rin) * PRS
                                      + (grp >> 1) * 16);
    const uint32_t b_off = (uint32_t)((wn * 32 + (grp >> 1) * 8 + rin) * PRS
                                      + (grp & 1) * 16);

    const int KT = K >> 5;

    auto issue_stage = [&](int kt) {
        const uint32_t sb = smu + (uint32_t)((kt & 1) * P_STAGE);
        const int k0 = kt * 32;
#pragma unroll
        for (int i = 0; i < 6; i++) {
            int u = tid + i * 256;
            if (u < 1024) {
                int plane = u >> 9, idx = u & 511;
                int row = idx >> 2, seg = idx & 3;
                const __nv_bfloat16* src = (plane ? Alo : Ahi)
                    + (size_t)(brow + row) * K + k0 + seg * 8;
                cp16(sb + P_AHI + (uint32_t)(plane * 10240 + row * PRS + seg * 16), src);
            } else {
                int v = u - 1024;
                int plane = v >> 8, idx = v & 255;
                int row = idx >> 2, seg = idx & 3;
                const __nv_bfloat16* src = (plane ? Wlo : Whi)
                    + (size_t)(bcol + row) * K + k0 + seg * 8;
                cp16(sb + P_BHI + (uint32_t)(plane * 5120 + row * PRS + seg * 16), src);
            }
        }
        cp_commit();
    };

    issue_stage(0);
    for (int kt = 0; kt < KT; kt++) {
        if (kt + 1 < KT) {
            issue_stage(kt + 1);
            asm volatile("cp.async.wait_group 1;");
        } else {
            asm volatile("cp.async.wait_group 0;");
        }
        __syncthreads();
        const uint32_t sb = smu + (uint32_t)((kt & 1) * P_STAGE);
#pragma unroll
        for (int s = 0; s < 2; s++) {
            uint32_t ah[2][4], al[2][4], bh[2][4], bl[2][4];
#pragma unroll
            for (int mi = 0; mi < 2; mi++) {
                ldsm4(ah[mi], sb + P_AHI + a_off + (uint32_t)(mi * 16 * PRS + s * 32));
                ldsm4(al[mi], sb + P_ALO + a_off + (uint32_t)(mi * 16 * PRS + s * 32));
            }
#pragma unroll
            for (int nh = 0; nh < 2; nh++) {
                ldsm4(bh[nh], sb + P_BHI + b_off + (uint32_t)(nh * 16 * PRS + s * 32));
                ldsm4(bl[nh], sb + P_BLO + b_off + (uint32_t)(nh * 16 * PRS + s * 32));
            }
#pragma unroll
            for (int mi = 0; mi < 2; mi++)
#pragma unroll
                for (int nj = 0; nj < 4; nj++) {
                    const uint32_t* bhf = &bh[nj >> 1][(nj & 1) * 2];
                    const uint32_t* blf = &bl[nj >> 1][(nj & 1) * 2];
                    mma_bf16v(acc[mi][nj], ah[mi], bhf);
                    mma_bf16v(acc[mi][nj], ah[mi], blf);
                    mma_bf16v(acc[mi][nj], al[mi], bhf);
                }
        }
        __syncthreads();
    }

    const int gid = lane >> 2, tig = lane & 3;
#pragma unroll
    for (int mi = 0; mi < 2; mi++) {
        const int r0 = brow + wm * 32 + mi * 16 + gid;
#pragma unroll
        for (int nj = 0; nj < 4; nj++) {
            const int col = bcol + wn * 32 + nj * 8 + tig * 2;
            float bx = b0[col] + b1[col];
            float by = b0[col + 1] + b1[col + 1];
            *(float2*)&C[(size_t)r0 * HH + col] =
                make_float2(acc[mi][nj][0] + bx, acc[mi][nj][1] + by);
            *(float2*)&C[(size_t)(r0 + 8) * HH + col] =
                make_float2(acc[mi][nj][2] + bx, acc[mi][nj][3] + by);
        }
    }
}

// ---------------------------------------------------------------------------
// Persistent HMMA recurrent layer — R15 structure; count-spin barrier:
// arrive = atom.release.add on one hot word; observe = ld.acquire >= 32*(t+1).
// dom selects the barrier domain base (0 for layer 0, 4 for layer 1).
// ---------------------------------------------------------------------------
__global__ __launch_bounds__(NTHR, 1) void rnn_layer_tc(
    const float* __restrict__ pre,
    float* __restrict__ hbase,
    const float* __restrict__ Whh,
    int dom)
{
    extern __shared__ char smb[];
    const uint32_t smu = smem_u32(smb);

    const int tid  = threadIdx.x;
    const int wid  = tid >> 5;
    const int lane = tid & 31;
    const int cb   = blockIdx.x & (NCOLBLK - 1);
    const int rg   = blockIdx.x >> 5;            // row group 0..3
    const int bcol = cb * NCOLS;
    const int brow = rg * NROWS;
    unsigned int* cnt = &g_cnt[(dom + rg) * 32];

    // one-time W slice: fp32 -> bf16 hi/lo, [n][k] padded rows
    for (int i = tid; i < NCOLS * HH; i += NTHR) {
        int n = i >> 10;
        int k = i & 1023;
        float v = Whh[(size_t)(bcol + n) * HH + k];
        __nv_bfloat16 hi = __float2bfloat16(v);
        __nv_bfloat16 lo = __float2bfloat16(v - __bfloat162float(hi));
        *(__nv_bfloat16*)(smb + SM_WHI + n * WROWB + k * 2) = hi;
        *(__nv_bfloat16*)(smb + SM_WLO + n * WROWB + k * 2) = lo;
    }
    __syncthreads();

    const int nt = wid & 3;             // n-tile (8 cols)
    const int kg = wid >> 2;            // k-group (half of each chunk)

    const int grp = lane >> 3;
    const int rin = lane & 7;
    const uint32_t a_lane_off =
        (uint32_t)(((grp & 1) * 8 + rin) * CROWB + (grp >> 1) * 16);
    const uint32_t b4_off =
        (uint32_t)((nt * 8 + rin) * WROWB + grp * 16);

    const size_t row_stride = (size_t)TT * HH;
    const uint32_t scr = smu + SM_SCR + (uint32_t)((nt * 32 + lane) * 16);

    for (int t = 0; t < TT; t++) {
        float acc[6][4];
#pragma unroll
        for (int i = 0; i < 6; i++)
#pragma unroll
            for (int q = 0; q < 4; q++) acc[i][q] = 0.f;

        if (t > 0) {
            // ---- stage chunk 0 (k 0..511, hi+lo) ----
#pragma unroll
            for (int i = 0; i < 8; i++) {
                int u = tid + i * NTHR;           // 0..2047
                int plane = u >> 10;
                int idx = u & 1023;
                int row = idx >> 6;
                int ku  = idx & 63;
                uint32_t d = smu + SM_A0 + (uint32_t)(plane * CPLANE + row * CROWB + ku * 16);
                const __nv_bfloat16* src = (plane ? g_hlo : g_hhi)
                    + (size_t)(brow + row) * HH + ku * 8;
                cp16(d, src);
            }
            cp_commit();

            // ---- stage chunk 1 (k 512..1023) + pre tile ----
#pragma unroll
            for (int i = 0; i < 8; i++) {
                int u = tid + i * NTHR;
                int plane = u >> 10;
                int idx = u & 1023;
                int row = idx >> 6;
                int ku  = idx & 63;
                uint32_t d = smu + SM_A1 + (uint32_t)(plane * CPLANE + row * CROWB + ku * 16);
                const __nv_bfloat16* src = (plane ? g_hlo : g_hhi)
                    + (size_t)(brow + row) * HH + 512 + ku * 8;
                cp16(d, src);
            }
            if (tid < 128) {
                int row = tid >> 3, q = tid & 7;
                cp16(smu + SM_PRE + (uint32_t)(row * 128 + q * 16),
                     &pre[(size_t)(brow + row) * row_stride + (size_t)t * HH
                          + bcol + q * 4]);
            }
            cp_commit();

            // ---- MMA chunk 0, then chunk 1 ----
            asm volatile("cp.async.wait_group 1;");
            __syncthreads();
#pragma unroll
            for (int c = 0; c < 2; c++) {
                if (c == 1) {
                    asm volatile("cp.async.wait_group 0;");
                    __syncthreads();
                }
                const uint32_t ab = smu + (c ? SM_A1 : SM_A0) + a_lane_off
                                  + (uint32_t)(kg * 512);
                const uint32_t bb_hi = smu + SM_WHI + b4_off
                                     + (uint32_t)(c * 1024 + kg * 512);
                const uint32_t bb_lo = smu + SM_WLO + b4_off
                                     + (uint32_t)(c * 1024 + kg * 512);
#pragma unroll
                for (int p2 = 0; p2 < 8; p2++) {      // k32 groups
                    uint32_t bh[4], bl[4];
                    ldsm4(bh, bb_hi + p2 * 64);
                    ldsm4(bl, bb_lo + p2 * 64);
#pragma unroll
                    for (int e = 0; e < 2; e++) {
                        const int s = p2 * 2 + e;
                        uint32_t ah[4], al[4];
                        ldsm4(ah, ab + s * 32);
                        ldsm4(al, ab + CPLANE + s * 32);
                        const uint32_t* bhf = &bh[e * 2];
                        const uint32_t* blf = &bl[e * 2];
                        mma_bf16v(acc[(s & 1) * 3 + 0], ah, bhf);
                        mma_bf16v(acc[(s & 1) * 3 + 1], ah, blf);
                        mma_bf16v(acc[(s & 1) * 3 + 2], al, bhf);
                    }
                }
            }
        } else {
            // t == 0: just prefetch the pre tile
            if (tid < 128) {
                int row = tid >> 3, q = tid & 7;
                cp16(smu + SM_PRE + (uint32_t)(row * 128 + q * 16),
                     &pre[(size_t)(brow + row) * row_stride + bcol + q * 4]);
            }
            cp_commit();
            asm volatile("cp.async.wait_group 0;");
            __syncthreads();
        }

        // ---- merge k-group partials ----
        float c0 = 0.f, c1 = 0.f, c2 = 0.f, c3 = 0.f;
#pragma unroll
        for (int i = 0; i < 6; i++) {
            c0 += acc[i][0]; c1 += acc[i][1];
            c2 += acc[i][2]; c3 += acc[i][3];
        }
        if (t > 0) {
            if (kg == 1) {
                asm volatile("st.shared.v4.f32 [%0], {%1,%2,%3,%4};"
                             :: "r"(scr), "f"(c0), "f"(c1), "f"(c2), "f"(c3)
                             : "memory");
            }
            __syncthreads();
        }

        // ---- epilogue (kg==0 warps): h = tanh(pre + acc) ----
        const int gid = lane >> 2;
        const int tig = lane & 3;
        const int m0 = brow + gid;
        const int m1 = m0 + 8;
        const int nc = bcol + nt * 8 + tig * 2;
        float h00, h01, h10, h11;

        if (kg == 0) {
            if (t > 0) {
                float s0, s1, s2, s3;
                asm volatile("ld.shared.v4.f32 {%0,%1,%2,%3}, [%4];"
                             : "=f"(s0), "=f"(s1), "=f"(s2), "=f"(s3) : "r"(scr));
                c0 += s0; c1 += s1; c2 += s2; c3 += s3;
            }
            const uint32_t pofs = (uint32_t)((nt * 8 + tig * 2) * 4);
            float2 p0 = *(const float2*)(smb + SM_PRE + gid * 128 + pofs);
            float2 p1 = *(const float2*)(smb + SM_PRE + (gid + 8) * 128 + pofs);
            h00 = tanhf(p0.x + c0);
            h01 = tanhf(p0.y + c1);
            h10 = tanhf(p1.x + c2);
            h11 = tanhf(p1.y + c3);

            // state for next step (what peer blocks need) — store FIRST
            __nv_bfloat16 e00 = __float2bfloat16(h00);
            __nv_bfloat16 e01 = __float2bfloat16(h01);
            __nv_bfloat16 e10 = __float2bfloat16(h10);
            __nv_bfloat16 e11 = __float2bfloat16(h11);
            *(uint32_t*)&g_hhi[(size_t)m0 * HH + nc] = pack_bf16(h00, h01);
            *(uint32_t*)&g_hhi[(size_t)m1 * HH + nc] = pack_bf16(h10, h11);
            *(uint32_t*)&g_hlo[(size_t)m0 * HH + nc] =
                pack_bf16(h00 - __bfloat162float(e00), h01 - __bfloat162float(e01));
            *(uint32_t*)&g_hlo[(size_t)m1 * HH + nc] =
                pack_bf16(h10 - __bfloat162float(e10), h11 - __bfloat162float(e11));
        }

        // ---- count-spin barrier: release-arrive; acquire-poll >= target ----
        __syncthreads();
        if (tid == 0) atom_add_release(cnt);

        if (kg == 0) {
            const size_t o0 = (size_t)m0 * row_stride + (size_t)t * HH + nc;
            const size_t o1 = (size_t)m1 * row_stride + (size_t)t * HH + nc;
            *(float2*)&hbase[o0] = make_float2(h00, h01);
            *(float2*)&hbase[o1] = make_float2(h10, h11);
        }

        if (tid == 0) {
            const unsigned int want = (unsigned int)NCOLBLK * (unsigned int)(t + 1);
            while (ld_acquire(cnt) < want) { }
        }
        __syncthreads();
    }
}

// ---------------------------------------------------------------------------
__global__ void finalize_kernel(float* __restrict__ out)
{
    int i = blockIdx.x * blockDim.x + threadIdx.x;   // over B*H
    if (i >= BB * HH) return;
    int b = i / HH;
    int h = i - b * HH;
    float* hfin = out + (size_t)BB * TT * HH;
    size_t src = (size_t)b * TT * HH + (size_t)(TT - 1) * HH + h;
    hfin[i] = g_buf0[src];
    hfin[(size_t)BB * HH + i] = out[src];
}

// ---------------------------------------------------------------------------

extern "C" void kernel_launch(void* const* d_in, const int* in_sizes, int n_in,
                              void* d_out, int out_size)
{
    const float* x      = (const float*)d_in[0];
    const float* W_ih0  = (const float*)d_in[1];
    const float* W_hh0  = (const float*)d_in[2];
    const float* b_ih0  = (const float*)d_in[3];
    const float* b_hh0  = (const float*)d_in[4];
    const float* W_ih1  = (const float*)d_in[5];
    const float* W_hh1  = (const float*)d_in[6];
    const float* b_ih1  = (const float*)d_in[7];
    const float* b_hh1  = (const float*)d_in[8];
    float* out = (float*)d_out;

    void* p;
    cudaGetSymbolAddress(&p, g_buf0); float* buf0 = (float*)p;
    cudaGetSymbolAddress(&p, g_buf1); float* buf1 = (float*)p;
    cudaGetSymbolAddress(&p, g_ahi);  __nv_bfloat16* ahi = (__nv_bfloat16*)p;
    cudaGetSymbolAddress(&p, g_alo);  __nv_bfloat16* alo = (__nv_bfloat16*)p;
    cudaGetSymbolAddress(&p, g_whi);  __nv_bfloat16* whi = (__nv_bfloat16*)p;
    cudaGetSymbolAddress(&p, g_wlo);  __nv_bfloat16* wlo = (__nv_bfloat16*)p;

    cudaFuncSetAttribute(rnn_layer_tc,
                         cudaFuncAttributeMaxDynamicSharedMemorySize, SM_TOTAL);
    cudaFuncSetAttribute(hmma_pre_gemm,
                         cudaFuncAttributeMaxDynamicSharedMemorySize, P_SMEM);

    // 1) split X and W_ih0 to bf16 hi/lo (first launch also zeroes barriers)
    conv_split_kernel<<<1024, 256>>>(x, ahi, alo, BB * TT * DIN, 1);
    conv_split_kernel<<<256, 256>>>(W_ih0, whi, wlo, HH * DIN, 0);

    // 2) pre0 = X @ W_ih0^T + b_ih0 + b_hh0
    {
        dim3 grid(HH / 64, (BB * TT) / 128);
        hmma_pre_gemm<<<grid, 256, P_SMEM>>>(ahi, alo, whi, wlo,
                                             b_ih0, b_hh0, buf0, DIN);
    }

    // 3) layer-0 recurrence (in place over buf0), barrier domains 0-3
    rnn_layer_tc<<<RNBLK, NTHR, SM_TOTAL>>>(buf0, buf0, W_hh0, 0);

    // 4) split H0 and W_ih1, then pre1 = H0 @ W_ih1^T + b_ih1 + b_hh1
    conv_split_kernel<<<1024, 256>>>(buf0, ahi, alo, BB * TT * HH, 0);
    conv_split_kernel<<<512, 256>>>(W_ih1, whi, wlo, HH * HH, 0);
    {
        dim3 grid(HH / 64, (BB * TT) / 128);
        hmma_pre_gemm<<<grid, 256, P_SMEM>>>(ahi, alo, whi, wlo,
                                             b_ih1, b_hh1, buf1, HH);
    }

    // 5) layer-1 recurrence (writes h1 into outputs), barrier domains 4-7
    rnn_layer_tc<<<RNBLK, NTHR, SM_TOTAL>>>(buf1, out, W_hh1, 4);

    // 6) h_final
    finalize_kernel<<<(BB * HH + 255) / 256, 256>>>(out);
}